// round 1
// baseline (speedup 1.0000x reference)
#include <cuda_runtime.h>
#include <math.h>
#include <stdint.h>

#define FEAT 256
#define KTOT 2304   // 9 * 256, k = rs*256 + ci

// ---------------- scratch (static device globals; no runtime allocation) ----
__device__ float g_bufA[FEAT * 160 * 256];          // 10.49 M floats
__device__ float g_bufB[FEAT * 160 * 256];
__device__ float g_bufP[5242880];                   // split-K partials (max 32*256*640)
__device__ float g_wt[12 * KTOT * FEAT + KTOT * 81 + KTOT * 4 + KTOT * 36];
__device__ float g_aff[2 * FEAT];                   // per-channel GN affine (a, b)
__device__ float g_biasA[81];                       // concat(pcls_b[80], pctr_b[1])

// ---------------- weight transpose: w[co][ci][3][3] -> wt[k][co], k=rs*256+ci
__global__ void transpose_w(const float* __restrict__ w, float* __restrict__ wt,
                            int Cout, int coStride, int coOff) {
    int idx = blockIdx.x * blockDim.x + threadIdx.x;
    if (idx >= Cout * KTOT) return;
    int co = idx / KTOT;
    int k  = idx - co * KTOT;
    int rs = k >> 8;
    int ci = k & 255;
    wt[(size_t)k * coStride + coOff + co] = w[(size_t)co * KTOT + ci * 9 + rs];
}

__global__ void build_biasA(const float* __restrict__ bc, const float* __restrict__ bt,
                            float* __restrict__ out) {
    int i = threadIdx.x;
    if (i < 80) out[i] = bc[i];
    else if (i == 80) out[80] = bt[0];
}

// ---------------- GroupNorm stats: per group (32), produce per-channel a,b ---
__global__ void gn_stats(const float* __restrict__ y, const float* __restrict__ g,
                         const float* __restrict__ b, float* __restrict__ aff, int HW) {
    __shared__ double sh[256], sh2[256];
    int tid = threadIdx.x;
    int grp = blockIdx.x;
    const float* base = y + (size_t)grp * 8 * HW;
    int n = 8 * HW;
    double s = 0.0, s2 = 0.0;
    for (int i = tid; i < n; i += 256) {
        double v = (double)base[i];
        s += v; s2 += v * v;
    }
    sh[tid] = s; sh2[tid] = s2;
    __syncthreads();
    for (int o = 128; o > 0; o >>= 1) {
        if (tid < o) { sh[tid] += sh[tid + o]; sh2[tid] += sh2[tid + o]; }
        __syncthreads();
    }
    if (tid < 8) {
        double mean = sh[0] / n;
        double var  = sh2[0] / n - mean * mean;
        int c = grp * 8 + tid;
        float a = (float)((double)g[c] * rsqrt(var + 1e-5));
        aff[c]        = a;
        aff[FEAT + c] = b[c] - (float)mean * a;
    }
}

// ---------------- implicit-GEMM 3x3 conv tile: 128 px x 128 co x 8 k --------
// mode 0: raw write (tower / split-K partial); mode 1: +bias with co>=split
// routed to out2; mode 2: exp((v+bias)*scale).
__global__ __launch_bounds__(256, 2)
void conv_k(const float* __restrict__ x, const float* __restrict__ wt,
            const float* __restrict__ aff,
            float* __restrict__ out, float* __restrict__ out2,
            int H, int W, int Cout, int coStride, int chunk,
            int mode, const float* __restrict__ bias,
            const float* __restrict__ scale_ptr, int split) {
    const int HW = H * W;
    __shared__ __align__(16) float Xs[2][8][128];
    __shared__ __align__(16) float Ws[2][8][128];
    __shared__ float sA[FEAT], sB[FEAT];

    int tid = threadIdx.x;
    int px0 = blockIdx.x * 128;
    int co0 = blockIdx.y * 128;
    int kb  = blockIdx.z * chunk;
    int ke  = kb + chunk; if (ke > KTOT) ke = KTOT;

    bool hasAff = (aff != nullptr);
    if (hasAff) {
        for (int i = tid; i < FEAT; i += 256) { sA[i] = aff[i]; sB[i] = aff[FEAT + i]; }
    }

    int lpx = tid & 127;
    int lkk = tid >> 7;     // 0 or 1; kk = lkk + 2*j
    int p = px0 + lpx;
    bool pv = p < HW;
    int h = 0, w = 0;
    if (pv) { h = p / W; w = p - h * W; }

    float acc[8][8];
#pragma unroll
    for (int i = 0; i < 8; i++)
#pragma unroll
        for (int j = 0; j < 8; j++) acc[i][j] = 0.f;

    float xr[4], wr[4];

    auto loadG = [&](int k0) {
        int rs = k0 >> 8;
        int r = rs / 3, s = rs - 3 * (rs / 3);
        int hh = h + r - 1, ww = w + s - 1;
        bool v = pv && hh >= 0 && hh < H && ww >= 0 && ww < W;
        int base = hh * W + ww;
        int ci0 = k0 & 255;
#pragma unroll
        for (int j = 0; j < 4; j++) {
            int kk = lkk + 2 * j;
            int k = k0 + kk;
            float val = 0.f;
            if (v && k < ke) {
                int ci = ci0 + kk;
                val = x[(size_t)ci * HW + base];
                if (hasAff) val = fmaxf(fmaf(val, sA[ci], sB[ci]), 0.f);
            }
            xr[j] = val;
        }
#pragma unroll
        for (int j = 0; j < 4; j++) {
            int kk = lkk + 2 * j;
            int k = k0 + kk;
            int co = co0 + lpx;
            float val = 0.f;
            if (k < ke && co < Cout) val = wt[(size_t)k * coStride + co];
            wr[j] = val;
        }
    };
    auto storeS = [&](int buf) {
#pragma unroll
        for (int j = 0; j < 4; j++) {
            Xs[buf][lkk + 2 * j][lpx] = xr[j];
            Ws[buf][lkk + 2 * j][lpx] = wr[j];
        }
    };

    int row4 = (tid >> 4) << 2;
    int col4 = (tid & 15) << 2;

    auto compute = [&](int cb) {
#pragma unroll
        for (int kk = 0; kk < 8; kk++) {
            float a[8], b[8];
            float4 t0 = *(const float4*)&Ws[cb][kk][row4];
            float4 t1 = *(const float4*)&Ws[cb][kk][64 + row4];
            float4 t2 = *(const float4*)&Xs[cb][kk][col4];
            float4 t3 = *(const float4*)&Xs[cb][kk][64 + col4];
            a[0] = t0.x; a[1] = t0.y; a[2] = t0.z; a[3] = t0.w;
            a[4] = t1.x; a[5] = t1.y; a[6] = t1.z; a[7] = t1.w;
            b[0] = t2.x; b[1] = t2.y; b[2] = t2.z; b[3] = t2.w;
            b[4] = t3.x; b[5] = t3.y; b[6] = t3.z; b[7] = t3.w;
#pragma unroll
            for (int i = 0; i < 8; i++)
#pragma unroll
                for (int j = 0; j < 8; j++)
                    acc[i][j] = fmaf(a[i], b[j], acc[i][j]);
        }
    };

    __syncthreads();
    loadG(kb);
    storeS(0);
    __syncthreads();
    int cur = 0;
    for (int k0 = kb + 8; k0 < ke; k0 += 8) {
        loadG(k0);
        compute(cur);
        storeS(cur ^ 1);
        __syncthreads();
        cur ^= 1;
    }
    compute(cur);

    // epilogue
    float scl = 1.f;
    if (mode == 2) scl = *scale_ptr;
    size_t zoff = (size_t)blockIdx.z * (size_t)Cout * HW;
#pragma unroll
    for (int i = 0; i < 8; i++) {
        int col_co = (i < 4) ? (row4 + i) : (64 + row4 + i - 4);
        int co = co0 + col_co;
        if (co >= Cout) continue;
        float bv = (mode != 0 && bias != nullptr) ? bias[co] : 0.f;
        float* ob = out;
        int coo = co;
        if (mode == 1 && co >= split) { ob = out2; coo = co - split; }
#pragma unroll
        for (int j = 0; j < 8; j++) {
            int pl = (j < 4) ? (col4 + j) : (64 + col4 + j - 4);
            int pp = px0 + pl;
            if (pp >= HW) continue;
            float v = acc[i][j];
            if (mode == 1) v += bv;
            else if (mode == 2) v = expf((v + bv) * scl);
            ob[zoff + (size_t)coo * HW + pp] = v;
        }
    }
}

// ---------------- split-K reduce with fused epilogue -------------------------
__global__ void reduce_ep(const float* __restrict__ part, int S, int Cout, int HW,
                          float* __restrict__ out, float* __restrict__ out2,
                          int mode, const float* __restrict__ bias,
                          const float* __restrict__ scale_ptr, int split) {
    int i = blockIdx.x * blockDim.x + threadIdx.x;
    int CHW = Cout * HW;
    if (i >= CHW) return;
    float s = 0.f;
    for (int j = 0; j < S; j++) s += part[(size_t)j * CHW + i];
    if (mode == 0) { out[i] = s; return; }
    int co = i / HW;
    float bv = (bias != nullptr) ? bias[co] : 0.f;
    if (mode == 2) { out[i] = expf((s + bv) * (*scale_ptr)); return; }
    // mode 1
    int p = i - co * HW;
    if (co >= split) out2[(size_t)(co - split) * HW + p] = s + bv;
    else             out [(size_t)co * HW + p]           = s + bv;
}

// ---------------- host orchestration ----------------------------------------
extern "C" void kernel_launch(void* const* d_in, const int* in_sizes, int n_in,
                              void* d_out, int out_size) {
    (void)in_sizes; (void)n_in; (void)out_size;
    const float* feat[5];
    for (int l = 0; l < 5; l++) feat[l] = (const float*)d_in[l];
    const float* tw[3] = {(const float*)d_in[5], (const float*)d_in[8], (const float*)d_in[11]};
    const float* tg[3] = {(const float*)d_in[6], (const float*)d_in[9], (const float*)d_in[12]};
    const float* tb[3] = {(const float*)d_in[7], (const float*)d_in[10], (const float*)d_in[13]};
    const float* pcls_w = (const float*)d_in[14];
    const float* pcls_b = (const float*)d_in[15];
    const float* preg_w = (const float*)d_in[16];
    const float* preg_b = (const float*)d_in[17];
    const float* pmsk_w = (const float*)d_in[18];
    const float* pmsk_b = (const float*)d_in[19];
    const float* pctr_w = (const float*)d_in[20];
    const float* pctr_b = (const float*)d_in[21];
    const float* sc_bbox = (const float*)d_in[22];
    const float* sc_mask = (const float*)d_in[23];
    float* outf = (float*)d_out;

    float *bufA, *bufB, *bufP, *wt, *aff, *biasA;
    cudaGetSymbolAddress((void**)&bufA, g_bufA);
    cudaGetSymbolAddress((void**)&bufB, g_bufB);
    cudaGetSymbolAddress((void**)&bufP, g_bufP);
    cudaGetSymbolAddress((void**)&wt, g_wt);
    cudaGetSymbolAddress((void**)&aff, g_aff);
    cudaGetSymbolAddress((void**)&biasA, g_biasA);

    // transpose all weights to [k][co]
    for (int t = 0; t < 3; t++)
        for (int i = 0; i < 4; i++)
            transpose_w<<<(FEAT * KTOT + 255) / 256, 256>>>(
                tw[t] + (size_t)i * FEAT * KTOT,
                wt + (size_t)(t * 4 + i) * KTOT * FEAT, FEAT, FEAT, 0);
    float* wtA = wt + (size_t)12 * KTOT * FEAT;
    float* wtB = wtA + (size_t)KTOT * 81;
    float* wtC = wtB + (size_t)KTOT * 4;
    transpose_w<<<(80 * KTOT + 255) / 256, 256>>>(pcls_w, wtA, 80, 81, 0);
    transpose_w<<<(1 * KTOT + 255) / 256, 256>>>(pctr_w, wtA, 1, 81, 80);
    transpose_w<<<(4 * KTOT + 255) / 256, 256>>>(preg_w, wtB, 4, 4, 0);
    transpose_w<<<(36 * KTOT + 255) / 256, 256>>>(pmsk_w, wtC, 36, 36, 0);
    build_biasA<<<1, 128>>>(pcls_b, pctr_b, biasA);

    static const int Hs[5] = {160, 80, 40, 20, 10};
    static const int Wss[5] = {256, 128, 64, 32, 16};
    static const int Sl[5] = {1, 2, 8, 32, 72};        // split-K factors (divide 288 steps)
    static const size_t PHW[5] = {0, 40960, 51200, 53760, 54400};
    const size_t TOT = 54560;
    const size_t clsBase = 0, bboxBase = 80 * TOT, ctrBase = 84 * TOT, maskBase = 85 * TOT;
    const int BIG = 1 << 30;

    for (int l = 0; l < 5; l++) {
        int H = Hs[l], W = Wss[l], HW = H * W;
        int S = Sl[l], chunk = KTOT / S;
        int gx = (HW + 127) / 128;
        for (int t = 0; t < 3; t++) {
            const float* xin = feat[l];
            const float* affp = nullptr;
            for (int i = 0; i < 4; i++) {
                float* yout = (i & 1) ? bufB : bufA;
                const float* wslot = wt + (size_t)(t * 4 + i) * KTOT * FEAT;
                if (S == 1) {
                    conv_k<<<dim3(gx, 2, 1), 256>>>(xin, wslot, affp, yout, nullptr,
                        H, W, FEAT, FEAT, chunk, 0, nullptr, nullptr, BIG);
                } else {
                    conv_k<<<dim3(gx, 2, S), 256>>>(xin, wslot, affp, bufP, nullptr,
                        H, W, FEAT, FEAT, chunk, 0, nullptr, nullptr, BIG);
                    reduce_ep<<<(FEAT * HW + 255) / 256, 256>>>(bufP, S, FEAT, HW,
                        yout, nullptr, 0, nullptr, nullptr, 0);
                }
                gn_stats<<<32, 256>>>(yout, tg[t] + i * FEAT, tb[t] + i * FEAT, aff, HW);
                xin = yout;
                affp = aff;
            }
            // prediction head for this tower
            int Cout, coStride, mode, split = BIG;
            const float* hwt; const float* bias; const float* scp = nullptr;
            float *o1, *o2 = nullptr;
            if (t == 0) {
                Cout = 81; coStride = 81; mode = 1; split = 80;
                hwt = wtA; bias = biasA;
                o1 = outf + clsBase + 80 * PHW[l];
                o2 = outf + ctrBase + PHW[l];
            } else if (t == 1) {
                Cout = 4; coStride = 4; mode = 2;
                hwt = wtB; bias = preg_b; scp = sc_bbox + l;
                o1 = outf + bboxBase + 4 * PHW[l];
            } else {
                Cout = 36; coStride = 36; mode = 2;
                hwt = wtC; bias = pmsk_b; scp = sc_mask + l;
                o1 = outf + maskBase + 36 * PHW[l];
            }
            if (S == 1) {
                conv_k<<<dim3(gx, 1, 1), 256>>>(xin, hwt, affp, o1, o2,
                    H, W, Cout, coStride, chunk, mode, bias, scp, split);
            } else {
                conv_k<<<dim3(gx, 1, S), 256>>>(xin, hwt, affp, bufP, nullptr,
                    H, W, Cout, coStride, chunk, 0, nullptr, nullptr, BIG);
                reduce_ep<<<(Cout * HW + 255) / 256, 256>>>(bufP, S, Cout, HW,
                    o1, o2, mode, bias, scp, split);
            }
        }
    }
}